// round 11
// baseline (speedup 1.0000x reference)
#include <cuda_runtime.h>
#include <cstdint>

// Shapes fixed by the reference: K=64, N=128, T=32768
#define KU   64
#define NU   128
#define EPSV 0.01f
#define INF_BITS 0x7F800000u

// Monotonic warp-retirement counter (32 warps per block). Never reset: a
// replay is complete exactly when count % (nblocks*32) == 0. For this bench
// nblocks*32 = 256 divides 2^32, so u32 wraparound preserves the modulus.
__device__ unsigned int g_retire = 0u;

__device__ __forceinline__ void retire_release(unsigned int* ctr) {
    asm volatile("red.release.gpu.global.add.u32 [%0], 1;"
                 :: "l"(ctr) : "memory");
}
__device__ __forceinline__ unsigned load_acquire(const unsigned int* ctr) {
    unsigned v;
    asm volatile("ld.acquire.gpu.global.u32 %0, [%1];" : "=r"(v) : "l"(ctr));
    return v;
}

// ---------------------------------------------------------------------------
// Single fused kernel, 1024 threads/block (32 warps), one float4 of t per
// thread. Each warp owns 2 units (16 lanes/unit, 4 LDG.128/thread, split
// accumulators => FMA chains of depth 4). Warp 0 funnels the 32 per-warp
// coefficient partials after one barrier; vsum overlaps phase 1 in warp 1.
// Common-path epilogue per warp: ballot + syncwarp + ONE fire-and-forget
// release-RED by lane0, then exit. Rare path (some element <= 0 or slow path
// used; never on this data): lowest flagged lane of each flagged warp spins
// until all warps retired, recomputes every element from inputs
// (bit-identical across fixers => benign write races), applies the shift.
// ---------------------------------------------------------------------------
__global__ void __launch_bounds__(1024)
fused_mgn_kernel(const float* __restrict__ t,
                 const float* __restrict__ W,
                 const float* __restrict__ b,
                 const float* __restrict__ V,
                 const float* __restrict__ a,
                 float* __restrict__ out,
                 int T, int vlen, int nblocks) {
    __shared__ float4   swc[32];    // per-warp coefficient partials {c0,c1,c2,c3}
    __shared__ unsigned sneg[32];   // per-warp "saw negative W/b" ballots
    __shared__ float    scoef[5];   // c0,c1,c2,c3,vsum

    const int tid  = threadIdx.x;
    const int wrp  = tid >> 5, lane = tid & 31;
    const int T4   = T >> 2;
    const int tail = T - (T4 << 2);
    const int i4   = blockIdx.x * 1024 + tid;

    // ---- Hoisted loads: t and a overlap the W/b load wave ----
    float4 tv4 = make_float4(0.f, 0.f, 0.f, 0.f);
    const bool have_t = (i4 < T4);
    if (have_t) tv4 = __ldg(&((const float4*)t)[i4]);
    const float av = __ldg(a);          // broadcast, off the critical path

    // ---- Phase 1: per-unit sums -> per-warp coefficient partials ----
    {
        // warp w owns units k = w*2, w*2+1; 16 lanes per unit.
        const int k = (wrp << 1) + (lane >> 4), inner = lane & 15;
        const float4* W4 = (const float4*)W;
        const float4* B4 = (const float4*)b;
        // split accumulators: chains of depth 4
        float s2a = 0.f, sba = 0.f, bba = 0.f;
        float s2b = 0.f, sbb = 0.f, bbb = 0.f;
        bool  neg = false;
        {
            const int idx0 = k * (NU/4) + inner;          // j=0, line-contiguous
            const int idx1 = idx0 + 16;                   // j=1
            const float4 w0  = __ldg(&W4[idx0]);
            const float4 b0  = __ldg(&B4[idx0]);
            const float4 w1  = __ldg(&W4[idx1]);
            const float4 b1  = __ldg(&B4[idx1]);
            #pragma unroll
            for (int c = 0; c < 4; ++c) {
                const float wv0 = (&w0.x)[c], bv0 = (&b0.x)[c];
                s2a = fmaf(wv0, wv0, s2a);
                sba = fmaf(wv0, bv0, sba);
                bba = fmaf(bv0, bv0, bba);
                neg |= (wv0 < 0.f) | (bv0 < 0.f);
                const float wv1 = (&w1.x)[c], bv1 = (&b1.x)[c];
                s2b = fmaf(wv1, wv1, s2b);
                sbb = fmaf(wv1, bv1, sbb);
                bbb = fmaf(bv1, bv1, bbb);
                neg |= (wv1 < 0.f) | (bv1 < 0.f);
            }
        }
        float s2 = s2a + s2b, sb = sba + sbb, bb = bba + bbb;
        // reduce within each 16-lane unit group
        #pragma unroll
        for (int off = 8; off; off >>= 1) {
            s2 += __shfl_down_sync(0xFFFFFFFFu, s2, off, 16);
            sb += __shfl_down_sync(0xFFFFFFFFu, sb, off, 16);
            bb += __shfl_down_sync(0xFFFFFFFFu, bb, off, 16);
        }
        // per-unit cubic contributions (valid at inner==0 lanes; zero elsewhere)
        float c0, c1, c2, c3;
        if (inner == 0) {
            c3 = 0.5f * s2 * s2;
            c2 = 1.5f * s2 * sb;
            c1 = fmaf(sb, sb, 0.5f * bb * s2);
            c0 = 0.5f * bb * sb;
        } else {
            c0 = c1 = c2 = c3 = 0.f;
        }
        // warp-wide sum across the 2 units (nonzero lanes 16 apart)
        c0 += __shfl_xor_sync(0xFFFFFFFFu, c0, 16);
        c1 += __shfl_xor_sync(0xFFFFFFFFu, c1, 16);
        c2 += __shfl_xor_sync(0xFFFFFFFFu, c2, 16);
        c3 += __shfl_xor_sync(0xFFFFFFFFu, c3, 16);
        const unsigned nb = __ballot_sync(0xFFFFFFFFu, neg);
        if (lane == 0) {
            swc[wrp]  = make_float4(c0, c1, c2, c3);
            sneg[wrp] = nb;
        }
    }

    // ---- vsum = sum(V*V): warp 1, independent chain overlapping phase 1 ----
    if (wrp == 1) {
        const int v4n = vlen >> 2;
        float v = 0.f;
        for (int i = lane; i < v4n; i += 32) {
            const float4 vv = __ldg(&((const float4*)V)[i]);
            v = fmaf(vv.x, vv.x, fmaf(vv.y, vv.y, fmaf(vv.z, vv.z, vv.w * vv.w)));
        }
        for (int i = (v4n << 2) + lane; i < vlen; i += 32) {
            const float s = __ldg(&V[i]);
            v = fmaf(s, s, v);
        }
        #pragma unroll
        for (int off = 16; off; off >>= 1)
            v += __shfl_xor_sync(0xFFFFFFFFu, v, off);
        if (lane == 0) scoef[4] = v;
    }
    __syncthreads();

    // ---- Phase 2: warp 0 funnels the 32 partials ----
    if (wrp == 0) {
        // transposed: float l of swc = coef (l&3) of warp (l>>2); four quarters
        const float* sf = (const float*)swc;
        float v = (sf[lane] + sf[lane + 32]) + (sf[lane + 64] + sf[lane + 96]);
        #pragma unroll
        for (int off = 4; off <= 16; off <<= 1)
            v += __shfl_xor_sync(0xFFFFFFFFu, v, off);
        if (lane < 4) scoef[lane] = v;             // lanes 0..3 -> c0..c3
    }
    __syncthreads();

    const float c0 = scoef[0], c1 = scoef[1], c2 = scoef[2], c3 = scoef[3];
    const float lin = scoef[4];
    unsigned negor = 0u;
    #pragma unroll
    for (int w = 0; w < 32; ++w) negor |= sneg[w];
    const bool wb_nonneg = (negor == 0u);

    // ---- Phase 3: evaluate one float4 of t per thread ----
    bool flag = false;   // this lane produced v<=0 or used the slow path
    if (have_t) {
        float4 o;
        #pragma unroll
        for (int j = 0; j < 4; ++j) {
            const float tv = (&tv4.x)[j];
            float v;
            if (wb_nonneg && tv >= 0.f) {
                // exact: relu is identity on this element's whole z-column
                v = av + fmaf(lin, tv,
                        fmaf(fmaf(fmaf(c3, tv, c2), tv, c1), tv, c0));
            } else {
                flag = true;
                // exact fallback: brute-force relu network for this element
                float nn = 0.f;
                for (int k = 0; k < KU; ++k) {
                    float prim = 0.f, gate = 0.f;
                    #pragma unroll 8
                    for (int n = 0; n < NU; ++n) {
                        const float wv = __ldg(&W[k * NU + n]);
                        const float bv = __ldg(&b[k * NU + n]);
                        const float r  = fmaxf(fmaf(wv, tv, bv), 0.f);
                        prim = fmaf(r, r, prim);
                        gate = fmaf(wv, r, gate);
                    }
                    nn = fmaf(0.5f * prim, gate, nn);
                }
                v = av + fmaf(lin, tv, nn);
            }
            flag |= (v <= 0.f);
            (&o.x)[j] = v;
        }
        ((float4*)out)[i4] = o;
    }
    // scalar tail (T not multiple of 4) handled by block 0
    if (blockIdx.x == 0 && tid < tail) {
        const int i = (T4 << 2) + tid;
        const float tv = t[i];
        float v;
        if (wb_nonneg && tv >= 0.f) {
            v = av + fmaf(lin, tv, fmaf(fmaf(fmaf(c3, tv, c2), tv, c1), tv, c0));
        } else {
            flag = true;
            float nn = 0.f;
            for (int k = 0; k < KU; ++k) {
                float prim = 0.f, gate = 0.f;
                for (int n = 0; n < NU; ++n) {
                    const float wv = __ldg(&W[k * NU + n]);
                    const float bv = __ldg(&b[k * NU + n]);
                    const float r  = fmaxf(fmaf(wv, tv, bv), 0.f);
                    prim = fmaf(r, r, prim);
                    gate = fmaf(wv, r, gate);
                }
                nn = fmaf(0.5f * prim, gate, nn);
            }
            v = av + fmaf(lin, tv, nn);
        }
        flag |= (v <= 0.f);
        out[i] = v;
    }

    // ---- Epilogue: per-warp fire-and-forget retire; no block barrier ----
    const unsigned wflag = __ballot_sync(0xFFFFFFFFu, flag);
    __syncwarp();   // warp-scope ordering: lanes' STGs happen-before lane0's RED
    if (lane == 0) retire_release(&g_retire);
    if (wflag == 0) return;                 // common path: warp exits, no waits

    // ---- Rare path: lowest flagged lane of this warp becomes a fixer ----
    if (lane != (__ffs(wflag) - 1)) return;

    const unsigned M = (unsigned)nblocks * 32u;    // warp retires per replay
    unsigned c;
    do { c = load_acquire(&g_retire); } while ((c % M) != 0u);

    // Recompute every element from inputs (identical ops => identical bits in
    // every fixer => benign same-value write races), find the exact min, then
    // rewrite out with the positif shift.
    float mn = __int_as_float(INF_BITS);
    for (int i = 0; i < T; ++i) {
        const float tv = t[i];
        float v;
        if (wb_nonneg && tv >= 0.f) {
            v = av + fmaf(lin, tv, fmaf(fmaf(fmaf(c3, tv, c2), tv, c1), tv, c0));
        } else {
            float nn = 0.f;
            for (int k = 0; k < KU; ++k) {
                float prim = 0.f, gate = 0.f;
                for (int n = 0; n < NU; ++n) {
                    const float wv = __ldg(&W[k * NU + n]);
                    const float bv = __ldg(&b[k * NU + n]);
                    const float r  = fmaxf(fmaf(wv, tv, bv), 0.f);
                    prim = fmaf(r, r, prim);
                    gate = fmaf(wv, r, gate);
                }
                nn = fmaf(0.5f * prim, gate, nn);
            }
            v = av + fmaf(lin, tv, nn);
        }
        mn = fminf(mn, v);
    }
    if (mn <= 0.f) {
        const float corr = EPSV - mn;
        for (int i = 0; i < T; ++i) {
            const float tv = t[i];
            float v;
            if (wb_nonneg && tv >= 0.f) {
                v = av + fmaf(lin, tv, fmaf(fmaf(fmaf(c3, tv, c2), tv, c1), tv, c0));
            } else {
                float nn = 0.f;
                for (int k = 0; k < KU; ++k) {
                    float prim = 0.f, gate = 0.f;
                    for (int n = 0; n < NU; ++n) {
                        const float wv = __ldg(&W[k * NU + n]);
                        const float bv = __ldg(&b[k * NU + n]);
                        const float r  = fmaxf(fmaf(wv, tv, bv), 0.f);
                        prim = fmaf(r, r, prim);
                        gate = fmaf(wv, r, gate);
                    }
                    nn = fmaf(0.5f * prim, gate, nn);
                }
                v = av + fmaf(lin, tv, nn);
            }
            out[i] = v + corr;
        }
    }
}

// ---------------------------------------------------------------------------
extern "C" void kernel_launch(void* const* d_in, const int* in_sizes, int n_in,
                              void* d_out, int out_size) {
    const float* t = (const float*)d_in[0];
    const float* W = (const float*)d_in[1];
    const float* b = (const float*)d_in[2];
    const float* V = (const float*)d_in[3];
    const float* a = (const float*)d_in[4];
    float* out = (float*)d_out;

    const int T    = in_sizes[0];
    const int vlen = in_sizes[3];

    const int T4 = T >> 2;
    int nblocks = (T4 + 1023) / 1024;
    if (nblocks < 1) nblocks = 1;

    fused_mgn_kernel<<<nblocks, 1024>>>(t, W, b, V, a, out, T, vlen, nblocks);
}

// round 12
// speedup vs baseline: 1.1886x; 1.1886x over previous
#include <cuda_runtime.h>
#include <cstdint>

// Shapes fixed by the reference: K=64, N=128, T=32768
#define KU   64
#define NU   128
#define EPSV 0.01f
#define INF_BITS 0x7F800000u

// Monotonic warp-retirement counter (16 warps per block). Never reset: a
// replay is complete exactly when count % (nblocks*16) == 0. For this bench
// nblocks*16 = 256 divides 2^32, so u32 wraparound preserves the modulus.
__device__ unsigned int g_retire = 0u;

__device__ __forceinline__ void retire_release(unsigned int* ctr) {
    asm volatile("red.release.gpu.global.add.u32 [%0], 1;"
                 :: "l"(ctr) : "memory");
}
__device__ __forceinline__ unsigned load_acquire(const unsigned int* ctr) {
    unsigned v;
    asm volatile("ld.acquire.gpu.global.u32 %0, [%1];" : "=r"(v) : "l"(ctr));
    return v;
}

// ---------------------------------------------------------------------------
// Single fused kernel, 512 threads/block (16 warps) — the measured-optimal
// shape (R10). One float4 of t per thread. Each warp owns 4 units (8
// lanes/unit, 8 LDG.128/thread, split accumulators => FMA chains of depth 8).
// Warp 0 funnels the 16 per-warp coefficient partials after one barrier;
// vsum overlaps phase 1 in warp 1. Common-path epilogue per warp: ballot +
// syncwarp + ONE fire-and-forget release-RED by lane0, then exit. Rare path
// (some element <= 0 or slow path used; never on this data): lowest flagged
// lane of each flagged warp spins until all warps retired, recomputes every
// element from inputs (bit-identical across fixers => benign write races),
// applies the positif shift.
// ---------------------------------------------------------------------------
__global__ void __launch_bounds__(512)
fused_mgn_kernel(const float* __restrict__ t,
                 const float* __restrict__ W,
                 const float* __restrict__ b,
                 const float* __restrict__ V,
                 const float* __restrict__ a,
                 float* __restrict__ out,
                 int T, int vlen, int nblocks) {
    __shared__ float4   swc[16];    // per-warp coefficient partials {c0,c1,c2,c3}
    __shared__ unsigned sneg[16];   // per-warp "saw negative W/b" ballots
    __shared__ float    scoef[5];   // c0,c1,c2,c3,vsum

    const int tid  = threadIdx.x;
    const int wrp  = tid >> 5, lane = tid & 31;
    const int T4   = T >> 2;
    const int tail = T - (T4 << 2);
    const int i4   = blockIdx.x * 512 + tid;

    // ---- Hoisted loads: t and a overlap the W/b load wave ----
    float4 tv4 = make_float4(0.f, 0.f, 0.f, 0.f);
    const bool have_t = (i4 < T4);
    if (have_t) tv4 = __ldg(&((const float4*)t)[i4]);
    const float av = __ldg(a);          // broadcast, off the critical path

    // ---- Phase 1: per-unit sums -> per-warp coefficient partials ----
    {
        // warp w owns units k = w*4 .. w*4+3; 8 lanes per unit.
        const int k = (wrp << 2) + (lane >> 3), inner = lane & 7;
        const float4* W4 = (const float4*)W;
        const float4* B4 = (const float4*)b;
        // split accumulators: chains of depth 8 instead of 16
        float s2a = 0.f, sba = 0.f, bba = 0.f;
        float s2b = 0.f, sbb = 0.f, bbb = 0.f;
        bool  neg = false;
        #pragma unroll
        for (int j = 0; j < 4; ++j) {              // 4 float4 per array
            const int idx = k * (NU/4) + j * 8 + inner;   // line-contiguous per j
            const float4 w  = __ldg(&W4[idx]);
            const float4 bv = __ldg(&B4[idx]);
            if (j & 1) {
                #pragma unroll
                for (int c = 0; c < 4; ++c) {
                    const float wv = (&w.x)[c], bvv = (&bv.x)[c];
                    s2b = fmaf(wv,  wv,  s2b);
                    sbb = fmaf(wv,  bvv, sbb);
                    bbb = fmaf(bvv, bvv, bbb);
                    neg |= (wv < 0.f) | (bvv < 0.f);
                }
            } else {
                #pragma unroll
                for (int c = 0; c < 4; ++c) {
                    const float wv = (&w.x)[c], bvv = (&bv.x)[c];
                    s2a = fmaf(wv,  wv,  s2a);
                    sba = fmaf(wv,  bvv, sba);
                    bba = fmaf(bvv, bvv, bba);
                    neg |= (wv < 0.f) | (bvv < 0.f);
                }
            }
        }
        float s2 = s2a + s2b, sb = sba + sbb, bb = bba + bbb;
        // reduce within each 8-lane unit group
        #pragma unroll
        for (int off = 4; off; off >>= 1) {
            s2 += __shfl_down_sync(0xFFFFFFFFu, s2, off, 8);
            sb += __shfl_down_sync(0xFFFFFFFFu, sb, off, 8);
            bb += __shfl_down_sync(0xFFFFFFFFu, bb, off, 8);
        }
        // per-unit cubic contributions (valid at inner==0 lanes; zero elsewhere)
        float c0, c1, c2, c3;
        if (inner == 0) {
            c3 = 0.5f * s2 * s2;
            c2 = 1.5f * s2 * sb;
            c1 = fmaf(sb, sb, 0.5f * bb * s2);
            c0 = 0.5f * bb * sb;
        } else {
            c0 = c1 = c2 = c3 = 0.f;
        }
        // warp-wide sum across the 4 units (nonzero lanes are 8 apart)
        #pragma unroll
        for (int off = 8; off <= 16; off <<= 1) {
            c0 += __shfl_xor_sync(0xFFFFFFFFu, c0, off);
            c1 += __shfl_xor_sync(0xFFFFFFFFu, c1, off);
            c2 += __shfl_xor_sync(0xFFFFFFFFu, c2, off);
            c3 += __shfl_xor_sync(0xFFFFFFFFu, c3, off);
        }
        const unsigned nb = __ballot_sync(0xFFFFFFFFu, neg);
        if (lane == 0) {
            swc[wrp]  = make_float4(c0, c1, c2, c3);
            sneg[wrp] = nb;
        }
    }

    // ---- vsum = sum(V*V): warp 1, independent chain overlapping phase 1 ----
    if (wrp == 1) {
        const int v4n = vlen >> 2;
        float v = 0.f;
        for (int i = lane; i < v4n; i += 32) {
            const float4 vv = __ldg(&((const float4*)V)[i]);
            v = fmaf(vv.x, vv.x, fmaf(vv.y, vv.y, fmaf(vv.z, vv.z, vv.w * vv.w)));
        }
        for (int i = (v4n << 2) + lane; i < vlen; i += 32) {
            const float s = __ldg(&V[i]);
            v = fmaf(s, s, v);
        }
        #pragma unroll
        for (int off = 16; off; off >>= 1)
            v += __shfl_xor_sync(0xFFFFFFFFu, v, off);
        if (lane == 0) scoef[4] = v;
    }
    __syncthreads();

    // ---- Phase 2: warp 0 funnels the 16 partials ----
    if (wrp == 0) {
        // transposed: float l of swc = coef (l&3) of warp (l>>2); two halves
        const float* sf = (const float*)swc;
        float v = sf[lane] + sf[lane + 32];
        #pragma unroll
        for (int off = 4; off <= 16; off <<= 1)
            v += __shfl_xor_sync(0xFFFFFFFFu, v, off);
        if (lane < 4) scoef[lane] = v;             // lanes 0..3 -> c0..c3
    }
    __syncthreads();

    const float c0 = scoef[0], c1 = scoef[1], c2 = scoef[2], c3 = scoef[3];
    const float lin = scoef[4];
    const uint4 n0 = ((const uint4*)sneg)[0];
    const uint4 n1 = ((const uint4*)sneg)[1];
    const uint4 n2 = ((const uint4*)sneg)[2];
    const uint4 n3 = ((const uint4*)sneg)[3];
    const bool wb_nonneg = !((n0.x | n0.y | n0.z | n0.w) |
                             (n1.x | n1.y | n1.z | n1.w) |
                             (n2.x | n2.y | n2.z | n2.w) |
                             (n3.x | n3.y | n3.z | n3.w));

    // ---- Phase 3: evaluate one float4 of t per thread ----
    bool flag = false;   // this lane produced v<=0 or used the slow path
    if (have_t) {
        float4 o;
        #pragma unroll
        for (int j = 0; j < 4; ++j) {
            const float tv = (&tv4.x)[j];
            float v;
            if (wb_nonneg && tv >= 0.f) {
                // exact: relu is identity on this element's whole z-column
                v = av + fmaf(lin, tv,
                        fmaf(fmaf(fmaf(c3, tv, c2), tv, c1), tv, c0));
            } else {
                flag = true;
                // exact fallback: brute-force relu network for this element
                float nn = 0.f;
                for (int k = 0; k < KU; ++k) {
                    float prim = 0.f, gate = 0.f;
                    #pragma unroll 8
                    for (int n = 0; n < NU; ++n) {
                        const float wv = __ldg(&W[k * NU + n]);
                        const float bv = __ldg(&b[k * NU + n]);
                        const float r  = fmaxf(fmaf(wv, tv, bv), 0.f);
                        prim = fmaf(r, r, prim);
                        gate = fmaf(wv, r, gate);
                    }
                    nn = fmaf(0.5f * prim, gate, nn);
                }
                v = av + fmaf(lin, tv, nn);
            }
            flag |= (v <= 0.f);
            (&o.x)[j] = v;
        }
        ((float4*)out)[i4] = o;
    }
    // scalar tail (T not multiple of 4) handled by block 0
    if (blockIdx.x == 0 && tid < tail) {
        const int i = (T4 << 2) + tid;
        const float tv = t[i];
        float v;
        if (wb_nonneg && tv >= 0.f) {
            v = av + fmaf(lin, tv, fmaf(fmaf(fmaf(c3, tv, c2), tv, c1), tv, c0));
        } else {
            flag = true;
            float nn = 0.f;
            for (int k = 0; k < KU; ++k) {
                float prim = 0.f, gate = 0.f;
                for (int n = 0; n < NU; ++n) {
                    const float wv = __ldg(&W[k * NU + n]);
                    const float bv = __ldg(&b[k * NU + n]);
                    const float r  = fmaxf(fmaf(wv, tv, bv), 0.f);
                    prim = fmaf(r, r, prim);
                    gate = fmaf(wv, r, gate);
                }
                nn = fmaf(0.5f * prim, gate, nn);
            }
            v = av + fmaf(lin, tv, nn);
        }
        flag |= (v <= 0.f);
        out[i] = v;
    }

    // ---- Epilogue: per-warp fire-and-forget retire; no block barrier ----
    const unsigned wflag = __ballot_sync(0xFFFFFFFFu, flag);
    __syncwarp();   // warp-scope ordering: lanes' STGs happen-before lane0's RED
    if (lane == 0) retire_release(&g_retire);
    if (wflag == 0) return;                 // common path: warp exits, no waits

    // ---- Rare path: lowest flagged lane of this warp becomes a fixer ----
    if (lane != (__ffs(wflag) - 1)) return;

    const unsigned M = (unsigned)nblocks * 16u;    // warp retires per replay
    unsigned c;
    do { c = load_acquire(&g_retire); } while ((c % M) != 0u);

    // Recompute every element from inputs (identical ops => identical bits in
    // every fixer => benign same-value write races), find the exact min, then
    // rewrite out with the positif shift.
    float mn = __int_as_float(INF_BITS);
    for (int i = 0; i < T; ++i) {
        const float tv = t[i];
        float v;
        if (wb_nonneg && tv >= 0.f) {
            v = av + fmaf(lin, tv, fmaf(fmaf(fmaf(c3, tv, c2), tv, c1), tv, c0));
        } else {
            float nn = 0.f;
            for (int k = 0; k < KU; ++k) {
                float prim = 0.f, gate = 0.f;
                for (int n = 0; n < NU; ++n) {
                    const float wv = __ldg(&W[k * NU + n]);
                    const float bv = __ldg(&b[k * NU + n]);
                    const float r  = fmaxf(fmaf(wv, tv, bv), 0.f);
                    prim = fmaf(r, r, prim);
                    gate = fmaf(wv, r, gate);
                }
                nn = fmaf(0.5f * prim, gate, nn);
            }
            v = av + fmaf(lin, tv, nn);
        }
        mn = fminf(mn, v);
    }
    if (mn <= 0.f) {
        const float corr = EPSV - mn;
        for (int i = 0; i < T; ++i) {
            const float tv = t[i];
            float v;
            if (wb_nonneg && tv >= 0.f) {
                v = av + fmaf(lin, tv, fmaf(fmaf(fmaf(c3, tv, c2), tv, c1), tv, c0));
            } else {
                float nn = 0.f;
                for (int k = 0; k < KU; ++k) {
                    float prim = 0.f, gate = 0.f;
                    for (int n = 0; n < NU; ++n) {
                        const float wv = __ldg(&W[k * NU + n]);
                        const float bv = __ldg(&b[k * NU + n]);
                        const float r  = fmaxf(fmaf(wv, tv, bv), 0.f);
                        prim = fmaf(r, r, prim);
                        gate = fmaf(wv, r, gate);
                    }
                    nn = fmaf(0.5f * prim, gate, nn);
                }
                v = av + fmaf(lin, tv, nn);
            }
            out[i] = v + corr;
        }
    }
}

// ---------------------------------------------------------------------------
extern "C" void kernel_launch(void* const* d_in, const int* in_sizes, int n_in,
                              void* d_out, int out_size) {
    const float* t = (const float*)d_in[0];
    const float* W = (const float*)d_in[1];
    const float* b = (const float*)d_in[2];
    const float* V = (const float*)d_in[3];
    const float* a = (const float*)d_in[4];
    float* out = (float*)d_out;

    const int T    = in_sizes[0];
    const int vlen = in_sizes[3];

    const int T4 = T >> 2;
    int nblocks = (T4 + 511) / 512;
    if (nblocks < 1) nblocks = 1;

    fused_mgn_kernel<<<nblocks, 512>>>(t, W, b, V, a, out, T, vlen, nblocks);
}

// round 13
// speedup vs baseline: 1.3029x; 1.0962x over previous
#include <cuda_runtime.h>
#include <cstdint>

// Shapes fixed by the reference: K=64, N=128, T=32768
#define KU   64
#define NU   128
#define EPSV 0.01f
#define INF_BITS 0x7F800000u

// Monotonic warp-retirement counter (16 warps per block). Never reset: a
// replay is complete exactly when count % (nblocks*16) == 0. For this bench
// nblocks*16 = 256 divides 2^32, so u32 wraparound preserves the modulus.
__device__ unsigned int g_retire = 0u;

__device__ __forceinline__ void retire_release(unsigned int* ctr) {
    asm volatile("red.release.gpu.global.add.u32 [%0], 1;"
                 :: "l"(ctr) : "memory");
}
__device__ __forceinline__ unsigned load_acquire(const unsigned int* ctr) {
    unsigned v;
    asm volatile("ld.acquire.gpu.global.u32 %0, [%1];" : "=r"(v) : "l"(ctr));
    return v;
}

// ---------------------------------------------------------------------------
// Single fused kernel, 512 threads/block (16 warps), ONE block barrier.
// One float4 of t per thread. Each warp owns 4 units (8 lanes/unit, 8
// LDG.128/thread, split accumulators => FMA chains of depth 8). After the
// single barrier, EVERY warp redundantly funnels the 16 per-warp coefficient
// partials in parallel (2 broadcast LDS + 3 xor-shuffles + 4 broadcasts) —
// no second barrier, no warp-0 serialization. Common-path epilogue per warp:
// ballot + syncwarp + ONE fire-and-forget release-RED by lane0, then exit.
// Rare path (some element <= 0 or slow path used; never on this data):
// lowest flagged lane of each flagged warp spins until all warps retired,
// recomputes every element from inputs (bit-identical across fixers =>
// benign write races), applies the positif shift.
// ---------------------------------------------------------------------------
__global__ void __launch_bounds__(512)
fused_mgn_kernel(const float* __restrict__ t,
                 const float* __restrict__ W,
                 const float* __restrict__ b,
                 const float* __restrict__ V,
                 const float* __restrict__ a,
                 float* __restrict__ out,
                 int T, int vlen, int nblocks) {
    __shared__ float4   swc[16];    // per-warp coefficient partials {c0,c1,c2,c3}
    __shared__ unsigned sneg[16];   // per-warp "saw negative W/b" ballots
    __shared__ float    svsum;      // vsum = sum(V*V)

    const int tid  = threadIdx.x;
    const int wrp  = tid >> 5, lane = tid & 31;
    const int T4   = T >> 2;
    const int tail = T - (T4 << 2);
    const int i4   = blockIdx.x * 512 + tid;

    // ---- Hoisted loads: t and a overlap the W/b load wave ----
    float4 tv4 = make_float4(0.f, 0.f, 0.f, 0.f);
    const bool have_t = (i4 < T4);
    if (have_t) tv4 = __ldg(&((const float4*)t)[i4]);
    const float av = __ldg(a);          // broadcast, off the critical path

    // ---- Phase 1: per-unit sums -> per-warp coefficient partials ----
    {
        // warp w owns units k = w*4 .. w*4+3; 8 lanes per unit.
        const int k = (wrp << 2) + (lane >> 3), inner = lane & 7;
        const float4* W4 = (const float4*)W;
        const float4* B4 = (const float4*)b;
        // split accumulators: chains of depth 8 instead of 16
        float s2a = 0.f, sba = 0.f, bba = 0.f;
        float s2b = 0.f, sbb = 0.f, bbb = 0.f;
        bool  neg = false;
        #pragma unroll
        for (int j = 0; j < 4; ++j) {              // 4 float4 per array
            const int idx = k * (NU/4) + j * 8 + inner;   // line-contiguous per j
            const float4 w  = __ldg(&W4[idx]);
            const float4 bv = __ldg(&B4[idx]);
            if (j & 1) {
                #pragma unroll
                for (int c = 0; c < 4; ++c) {
                    const float wv = (&w.x)[c], bvv = (&bv.x)[c];
                    s2b = fmaf(wv,  wv,  s2b);
                    sbb = fmaf(wv,  bvv, sbb);
                    bbb = fmaf(bvv, bvv, bbb);
                    neg |= (wv < 0.f) | (bvv < 0.f);
                }
            } else {
                #pragma unroll
                for (int c = 0; c < 4; ++c) {
                    const float wv = (&w.x)[c], bvv = (&bv.x)[c];
                    s2a = fmaf(wv,  wv,  s2a);
                    sba = fmaf(wv,  bvv, sba);
                    bba = fmaf(bvv, bvv, bba);
                    neg |= (wv < 0.f) | (bvv < 0.f);
                }
            }
        }
        float s2 = s2a + s2b, sb = sba + sbb, bb = bba + bbb;
        // reduce within each 8-lane unit group
        #pragma unroll
        for (int off = 4; off; off >>= 1) {
            s2 += __shfl_down_sync(0xFFFFFFFFu, s2, off, 8);
            sb += __shfl_down_sync(0xFFFFFFFFu, sb, off, 8);
            bb += __shfl_down_sync(0xFFFFFFFFu, bb, off, 8);
        }
        // per-unit cubic contributions (valid at inner==0 lanes; zero elsewhere)
        float c0, c1, c2, c3;
        if (inner == 0) {
            c3 = 0.5f * s2 * s2;
            c2 = 1.5f * s2 * sb;
            c1 = fmaf(sb, sb, 0.5f * bb * s2);
            c0 = 0.5f * bb * sb;
        } else {
            c0 = c1 = c2 = c3 = 0.f;
        }
        // warp-wide sum across the 4 units (nonzero lanes are 8 apart)
        #pragma unroll
        for (int off = 8; off <= 16; off <<= 1) {
            c0 += __shfl_xor_sync(0xFFFFFFFFu, c0, off);
            c1 += __shfl_xor_sync(0xFFFFFFFFu, c1, off);
            c2 += __shfl_xor_sync(0xFFFFFFFFu, c2, off);
            c3 += __shfl_xor_sync(0xFFFFFFFFu, c3, off);
        }
        const unsigned nb = __ballot_sync(0xFFFFFFFFu, neg);
        if (lane == 0) {
            swc[wrp]  = make_float4(c0, c1, c2, c3);
            sneg[wrp] = nb;
        }
    }

    // ---- vsum = sum(V*V): warp 1, independent chain overlapping phase 1 ----
    if (wrp == 1) {
        const int v4n = vlen >> 2;
        float v = 0.f;
        for (int i = lane; i < v4n; i += 32) {
            const float4 vv = __ldg(&((const float4*)V)[i]);
            v = fmaf(vv.x, vv.x, fmaf(vv.y, vv.y, fmaf(vv.z, vv.z, vv.w * vv.w)));
        }
        for (int i = (v4n << 2) + lane; i < vlen; i += 32) {
            const float s = __ldg(&V[i]);
            v = fmaf(s, s, v);
        }
        #pragma unroll
        for (int off = 16; off; off >>= 1)
            v += __shfl_xor_sync(0xFFFFFFFFu, v, off);
        if (lane == 0) svsum = v;
    }
    __syncthreads();     // the ONLY block barrier

    // ---- Phase 2: EVERY warp funnels the 16 partials in parallel ----
    // transposed: float l of swc = coef (l&3) of warp (l>>2); two halves.
    // xor-shuffles over {4,8,16} leave every lane holding the TOTAL of its
    // coef class (lane&3); lanes 0..3 hold c0..c3 -> broadcast by shuffle.
    float c0, c1, c2, c3;
    {
        const float* sf = (const float*)swc;
        float v = sf[lane] + sf[lane + 32];
        #pragma unroll
        for (int off = 4; off <= 16; off <<= 1)
            v += __shfl_xor_sync(0xFFFFFFFFu, v, off);
        c0 = __shfl_sync(0xFFFFFFFFu, v, 0);
        c1 = __shfl_sync(0xFFFFFFFFu, v, 1);
        c2 = __shfl_sync(0xFFFFFFFFu, v, 2);
        c3 = __shfl_sync(0xFFFFFFFFu, v, 3);
    }
    const float lin = svsum;                      // broadcast LDS
    const uint4 n0 = ((const uint4*)sneg)[0];
    const uint4 n1 = ((const uint4*)sneg)[1];
    const uint4 n2 = ((const uint4*)sneg)[2];
    const uint4 n3 = ((const uint4*)sneg)[3];
    const bool wb_nonneg = !((n0.x | n0.y | n0.z | n0.w) |
                             (n1.x | n1.y | n1.z | n1.w) |
                             (n2.x | n2.y | n2.z | n2.w) |
                             (n3.x | n3.y | n3.z | n3.w));

    // ---- Phase 3: evaluate one float4 of t per thread ----
    bool flag = false;   // this lane produced v<=0 or used the slow path
    if (have_t) {
        float4 o;
        #pragma unroll
        for (int j = 0; j < 4; ++j) {
            const float tv = (&tv4.x)[j];
            float v;
            if (wb_nonneg && tv >= 0.f) {
                // exact: relu is identity on this element's whole z-column
                v = av + fmaf(lin, tv,
                        fmaf(fmaf(fmaf(c3, tv, c2), tv, c1), tv, c0));
            } else {
                flag = true;
                // exact fallback: brute-force relu network for this element
                float nn = 0.f;
                for (int k = 0; k < KU; ++k) {
                    float prim = 0.f, gate = 0.f;
                    #pragma unroll 8
                    for (int n = 0; n < NU; ++n) {
                        const float wv = __ldg(&W[k * NU + n]);
                        const float bv = __ldg(&b[k * NU + n]);
                        const float r  = fmaxf(fmaf(wv, tv, bv), 0.f);
                        prim = fmaf(r, r, prim);
                        gate = fmaf(wv, r, gate);
                    }
                    nn = fmaf(0.5f * prim, gate, nn);
                }
                v = av + fmaf(lin, tv, nn);
            }
            flag |= (v <= 0.f);
            (&o.x)[j] = v;
        }
        ((float4*)out)[i4] = o;
    }
    // scalar tail (T not multiple of 4) handled by block 0
    if (blockIdx.x == 0 && tid < tail) {
        const int i = (T4 << 2) + tid;
        const float tv = t[i];
        float v;
        if (wb_nonneg && tv >= 0.f) {
            v = av + fmaf(lin, tv, fmaf(fmaf(fmaf(c3, tv, c2), tv, c1), tv, c0));
        } else {
            flag = true;
            float nn = 0.f;
            for (int k = 0; k < KU; ++k) {
                float prim = 0.f, gate = 0.f;
                for (int n = 0; n < NU; ++n) {
                    const float wv = __ldg(&W[k * NU + n]);
                    const float bv = __ldg(&b[k * NU + n]);
                    const float r  = fmaxf(fmaf(wv, tv, bv), 0.f);
                    prim = fmaf(r, r, prim);
                    gate = fmaf(wv, r, gate);
                }
                nn = fmaf(0.5f * prim, gate, nn);
            }
            v = av + fmaf(lin, tv, nn);
        }
        flag |= (v <= 0.f);
        out[i] = v;
    }

    // ---- Epilogue: per-warp fire-and-forget retire; no block barrier ----
    const unsigned wflag = __ballot_sync(0xFFFFFFFFu, flag);
    __syncwarp();   // warp-scope ordering: lanes' STGs happen-before lane0's RED
    if (lane == 0) retire_release(&g_retire);
    if (wflag == 0) return;                 // common path: warp exits, no waits

    // ---- Rare path: lowest flagged lane of this warp becomes a fixer ----
    if (lane != (__ffs(wflag) - 1)) return;

    const unsigned M = (unsigned)nblocks * 16u;    // warp retires per replay
    unsigned c;
    do { c = load_acquire(&g_retire); } while ((c % M) != 0u);

    // Recompute every element from inputs (identical ops => identical bits in
    // every fixer => benign same-value write races), find the exact min, then
    // rewrite out with the positif shift.
    float mn = __int_as_float(INF_BITS);
    for (int i = 0; i < T; ++i) {
        const float tv = t[i];
        float v;
        if (wb_nonneg && tv >= 0.f) {
            v = av + fmaf(lin, tv, fmaf(fmaf(fmaf(c3, tv, c2), tv, c1), tv, c0));
        } else {
            float nn = 0.f;
            for (int k = 0; k < KU; ++k) {
                float prim = 0.f, gate = 0.f;
                for (int n = 0; n < NU; ++n) {
                    const float wv = __ldg(&W[k * NU + n]);
                    const float bv = __ldg(&b[k * NU + n]);
                    const float r  = fmaxf(fmaf(wv, tv, bv), 0.f);
                    prim = fmaf(r, r, prim);
                    gate = fmaf(wv, r, gate);
                }
                nn = fmaf(0.5f * prim, gate, nn);
            }
            v = av + fmaf(lin, tv, nn);
        }
        mn = fminf(mn, v);
    }
    if (mn <= 0.f) {
        const float corr = EPSV - mn;
        for (int i = 0; i < T; ++i) {
            const float tv = t[i];
            float v;
            if (wb_nonneg && tv >= 0.f) {
                v = av + fmaf(lin, tv, fmaf(fmaf(fmaf(c3, tv, c2), tv, c1), tv, c0));
            } else {
                float nn = 0.f;
                for (int k = 0; k < KU; ++k) {
                    float prim = 0.f, gate = 0.f;
                    for (int n = 0; n < NU; ++n) {
                        const float wv = __ldg(&W[k * NU + n]);
                        const float bv = __ldg(&b[k * NU + n]);
                        const float r  = fmaxf(fmaf(wv, tv, bv), 0.f);
                        prim = fmaf(r, r, prim);
                        gate = fmaf(wv, r, gate);
                    }
                    nn = fmaf(0.5f * prim, gate, nn);
                }
                v = av + fmaf(lin, tv, nn);
            }
            out[i] = v + corr;
        }
    }
}

// ---------------------------------------------------------------------------
extern "C" void kernel_launch(void* const* d_in, const int* in_sizes, int n_in,
                              void* d_out, int out_size) {
    const float* t = (const float*)d_in[0];
    const float* W = (const float*)d_in[1];
    const float* b = (const float*)d_in[2];
    const float* V = (const float*)d_in[3];
    const float* a = (const float*)d_in[4];
    float* out = (float*)d_out;

    const int T    = in_sizes[0];
    const int vlen = in_sizes[3];

    const int T4 = T >> 2;
    int nblocks = (T4 + 511) / 512;
    if (nblocks < 1) nblocks = 1;

    fused_mgn_kernel<<<nblocks, 512>>>(t, W, b, V, a, out, T, vlen, nblocks);
}

// round 14
// speedup vs baseline: 1.3092x; 1.0048x over previous
#include <cuda_runtime.h>
#include <cstdint>

// Shapes fixed by the reference: K=64, N=128, T=32768
#define KU   64
#define NU   128
#define EPSV 0.01f
#define INF_BITS 0x7F800000u

// Monotonic warp-retirement counter (16 warps per block). Never reset: a
// replay is complete exactly when count % (nblocks*16) == 0. For this bench
// nblocks*16 = 256 divides 2^32, so u32 wraparound preserves the modulus.
__device__ unsigned int g_retire = 0u;

__device__ __forceinline__ void retire_release(unsigned int* ctr) {
    asm volatile("red.release.gpu.global.add.u32 [%0], 1;"
                 :: "l"(ctr) : "memory");
}
__device__ __forceinline__ unsigned load_acquire(const unsigned int* ctr) {
    unsigned v;
    asm volatile("ld.acquire.gpu.global.u32 %0, [%1];" : "=r"(v) : "l"(ctr));
    return v;
}

// ---------------------------------------------------------------------------
// Single fused kernel, 512 threads/block (16 warps), ONE block barrier.
// One float4 of t per thread. Each warp owns 4 units (8 lanes/unit, 8
// LDG.128/thread, split accumulators => FMA chains of depth 8). vsum is
// DISTRIBUTED: lanes 0-1 of every warp each dot one V float4 (loads issued at
// the top, overlapping the W/b wave); per-warp partials land in svw[16] and
// are folded into the SAME funnel shuffles as the coefficients (independent
// chain, pipelined). After the single barrier, every warp redundantly funnels
// in parallel — no second barrier, no straggler warp. Common-path epilogue
// per warp: ballot + syncwarp + ONE fire-and-forget release-RED by lane0,
// then exit. Rare path (some element <= 0 or slow path used; never on this
// data): lowest flagged lane of each flagged warp spins until all warps
// retired, recomputes every element from inputs (bit-identical across fixers
// => benign write races), applies the positif shift.
// ---------------------------------------------------------------------------
__global__ void __launch_bounds__(512)
fused_mgn_kernel(const float* __restrict__ t,
                 const float* __restrict__ W,
                 const float* __restrict__ b,
                 const float* __restrict__ V,
                 const float* __restrict__ a,
                 float* __restrict__ out,
                 int T, int vlen, int nblocks) {
    __shared__ float4   swc[16];    // per-warp coefficient partials {c0,c1,c2,c3}
    __shared__ unsigned sneg[16];   // per-warp "saw negative W/b" ballots
    __shared__ float    svw[16];    // per-warp vsum partials

    const int tid  = threadIdx.x;
    const int wrp  = tid >> 5, lane = tid & 31;
    const int T4   = T >> 2;
    const int tail = T - (T4 << 2);
    const int i4   = blockIdx.x * 512 + tid;

    // ---- Hoisted loads: t, a, and this warp's V slice overlap the W/b wave ----
    float4 tv4 = make_float4(0.f, 0.f, 0.f, 0.f);
    const bool have_t = (i4 < T4);
    if (have_t) tv4 = __ldg(&((const float4*)t)[i4]);
    const float av = __ldg(a);          // broadcast, off the critical path

    float vdot = 0.f;                   // this lane's vsum contribution
    {
        const int v4n = vlen >> 2;
        if (lane < 2) {
            for (int i = (wrp << 1) + lane; i < v4n; i += 32) {
                const float4 vv = __ldg(&((const float4*)V)[i]);
                vdot = fmaf(vv.x, vv.x,
                       fmaf(vv.y, vv.y, fmaf(vv.z, vv.z, vv.w * vv.w)));
            }
        } else if (lane == 2 && wrp == 0) {
            for (int i = v4n << 2; i < vlen; ++i) {   // scalar tail of V
                const float s = __ldg(&V[i]);
                vdot = fmaf(s, s, vdot);
            }
        }
    }

    // ---- Phase 1: per-unit sums -> per-warp coefficient partials ----
    {
        // warp w owns units k = w*4 .. w*4+3; 8 lanes per unit.
        const int k = (wrp << 2) + (lane >> 3), inner = lane & 7;
        const float4* W4 = (const float4*)W;
        const float4* B4 = (const float4*)b;
        // split accumulators: chains of depth 8 instead of 16
        float s2a = 0.f, sba = 0.f, bba = 0.f;
        float s2b = 0.f, sbb = 0.f, bbb = 0.f;
        bool  neg = false;
        #pragma unroll
        for (int j = 0; j < 4; ++j) {              // 4 float4 per array
            const int idx = k * (NU/4) + j * 8 + inner;   // line-contiguous per j
            const float4 w  = __ldg(&W4[idx]);
            const float4 bv = __ldg(&B4[idx]);
            if (j & 1) {
                #pragma unroll
                for (int c = 0; c < 4; ++c) {
                    const float wv = (&w.x)[c], bvv = (&bv.x)[c];
                    s2b = fmaf(wv,  wv,  s2b);
                    sbb = fmaf(wv,  bvv, sbb);
                    bbb = fmaf(bvv, bvv, bbb);
                    neg |= (wv < 0.f) | (bvv < 0.f);
                }
            } else {
                #pragma unroll
                for (int c = 0; c < 4; ++c) {
                    const float wv = (&w.x)[c], bvv = (&bv.x)[c];
                    s2a = fmaf(wv,  wv,  s2a);
                    sba = fmaf(wv,  bvv, sba);
                    bba = fmaf(bvv, bvv, bba);
                    neg |= (wv < 0.f) | (bvv < 0.f);
                }
            }
        }
        float s2 = s2a + s2b, sb = sba + sbb, bb = bba + bbb;
        // reduce within each 8-lane unit group
        #pragma unroll
        for (int off = 4; off; off >>= 1) {
            s2 += __shfl_down_sync(0xFFFFFFFFu, s2, off, 8);
            sb += __shfl_down_sync(0xFFFFFFFFu, sb, off, 8);
            bb += __shfl_down_sync(0xFFFFFFFFu, bb, off, 8);
        }
        // per-unit cubic contributions (valid at inner==0 lanes; zero elsewhere)
        float c0, c1, c2, c3;
        if (inner == 0) {
            c3 = 0.5f * s2 * s2;
            c2 = 1.5f * s2 * sb;
            c1 = fmaf(sb, sb, 0.5f * bb * s2);
            c0 = 0.5f * bb * sb;
        } else {
            c0 = c1 = c2 = c3 = 0.f;
        }
        // warp-wide sum across the 4 units (nonzero lanes are 8 apart);
        // vsum partial folds lanes 0..3 (contributions live in lanes 0-2)
        vdot += __shfl_xor_sync(0xFFFFFFFFu, vdot, 1);
        vdot += __shfl_xor_sync(0xFFFFFFFFu, vdot, 2);
        #pragma unroll
        for (int off = 8; off <= 16; off <<= 1) {
            c0 += __shfl_xor_sync(0xFFFFFFFFu, c0, off);
            c1 += __shfl_xor_sync(0xFFFFFFFFu, c1, off);
            c2 += __shfl_xor_sync(0xFFFFFFFFu, c2, off);
            c3 += __shfl_xor_sync(0xFFFFFFFFu, c3, off);
        }
        const unsigned nb = __ballot_sync(0xFFFFFFFFu, neg);
        if (lane == 0) {
            swc[wrp]  = make_float4(c0, c1, c2, c3);
            sneg[wrp] = nb;
            svw[wrp]  = vdot;
        }
    }
    __syncthreads();     // the ONLY block barrier

    // ---- Phase 2: EVERY warp funnels the 16 partials in parallel ----
    // Coef chain v: float l of swc = coef (l&3) of warp (l>>2); two halves.
    // vsum chain u: svw[m] + svw[8+m], m = lane>>2; xor offsets {4,8,16} flip
    // bits of m => u sums all 16 partials. Chains are independent (pipelined).
    float c0, c1, c2, c3, lin;
    {
        const float* sf = (const float*)swc;
        float v = sf[lane] + sf[lane + 32];
        float u = svw[lane >> 2] + svw[8 + (lane >> 2)];
        #pragma unroll
        for (int off = 4; off <= 16; off <<= 1) {
            v += __shfl_xor_sync(0xFFFFFFFFu, v, off);
            u += __shfl_xor_sync(0xFFFFFFFFu, u, off);
        }
        c0 = __shfl_sync(0xFFFFFFFFu, v, 0);
        c1 = __shfl_sync(0xFFFFFFFFu, v, 1);
        c2 = __shfl_sync(0xFFFFFFFFu, v, 2);
        c3 = __shfl_sync(0xFFFFFFFFu, v, 3);
        lin = u;                                  // every lane holds full vsum
    }
    const uint4 n0 = ((const uint4*)sneg)[0];
    const uint4 n1 = ((const uint4*)sneg)[1];
    const uint4 n2 = ((const uint4*)sneg)[2];
    const uint4 n3 = ((const uint4*)sneg)[3];
    const bool wb_nonneg = !((n0.x | n0.y | n0.z | n0.w) |
                             (n1.x | n1.y | n1.z | n1.w) |
                             (n2.x | n2.y | n2.z | n2.w) |
                             (n3.x | n3.y | n3.z | n3.w));

    // ---- Phase 3: evaluate one float4 of t per thread ----
    bool flag = false;   // this lane produced v<=0 or used the slow path
    if (have_t) {
        float4 o;
        #pragma unroll
        for (int j = 0; j < 4; ++j) {
            const float tv = (&tv4.x)[j];
            float v;
            if (wb_nonneg && tv >= 0.f) {
                // exact: relu is identity on this element's whole z-column
                v = av + fmaf(lin, tv,
                        fmaf(fmaf(fmaf(c3, tv, c2), tv, c1), tv, c0));
            } else {
                flag = true;
                // exact fallback: brute-force relu network for this element
                float nn = 0.f;
                for (int k = 0; k < KU; ++k) {
                    float prim = 0.f, gate = 0.f;
                    #pragma unroll 8
                    for (int n = 0; n < NU; ++n) {
                        const float wv = __ldg(&W[k * NU + n]);
                        const float bv = __ldg(&b[k * NU + n]);
                        const float r  = fmaxf(fmaf(wv, tv, bv), 0.f);
                        prim = fmaf(r, r, prim);
                        gate = fmaf(wv, r, gate);
                    }
                    nn = fmaf(0.5f * prim, gate, nn);
                }
                v = av + fmaf(lin, tv, nn);
            }
            flag |= (v <= 0.f);
            (&o.x)[j] = v;
        }
        ((float4*)out)[i4] = o;
    }
    // scalar tail (T not multiple of 4) handled by block 0
    if (blockIdx.x == 0 && tid < tail) {
        const int i = (T4 << 2) + tid;
        const float tv = t[i];
        float v;
        if (wb_nonneg && tv >= 0.f) {
            v = av + fmaf(lin, tv, fmaf(fmaf(fmaf(c3, tv, c2), tv, c1), tv, c0));
        } else {
            flag = true;
            float nn = 0.f;
            for (int k = 0; k < KU; ++k) {
                float prim = 0.f, gate = 0.f;
                for (int n = 0; n < NU; ++n) {
                    const float wv = __ldg(&W[k * NU + n]);
                    const float bv = __ldg(&b[k * NU + n]);
                    const float r  = fmaxf(fmaf(wv, tv, bv), 0.f);
                    prim = fmaf(r, r, prim);
                    gate = fmaf(wv, r, gate);
                }
                nn = fmaf(0.5f * prim, gate, nn);
            }
            v = av + fmaf(lin, tv, nn);
        }
        flag |= (v <= 0.f);
        out[i] = v;
    }

    // ---- Epilogue: per-warp fire-and-forget retire; no block barrier ----
    const unsigned wflag = __ballot_sync(0xFFFFFFFFu, flag);
    __syncwarp();   // warp-scope ordering: lanes' STGs happen-before lane0's RED
    if (lane == 0) retire_release(&g_retire);
    if (wflag == 0) return;                 // common path: warp exits, no waits

    // ---- Rare path: lowest flagged lane of this warp becomes a fixer ----
    if (lane != (__ffs(wflag) - 1)) return;

    const unsigned M = (unsigned)nblocks * 16u;    // warp retires per replay
    unsigned c;
    do { c = load_acquire(&g_retire); } while ((c % M) != 0u);

    // Recompute every element from inputs (identical ops => identical bits in
    // every fixer => benign same-value write races), find the exact min, then
    // rewrite out with the positif shift.
    float mn = __int_as_float(INF_BITS);
    for (int i = 0; i < T; ++i) {
        const float tv = t[i];
        float v;
        if (wb_nonneg && tv >= 0.f) {
            v = av + fmaf(lin, tv, fmaf(fmaf(fmaf(c3, tv, c2), tv, c1), tv, c0));
        } else {
            float nn = 0.f;
            for (int k = 0; k < KU; ++k) {
                float prim = 0.f, gate = 0.f;
                for (int n = 0; n < NU; ++n) {
                    const float wv = __ldg(&W[k * NU + n]);
                    const float bv = __ldg(&b[k * NU + n]);
                    const float r  = fmaxf(fmaf(wv, tv, bv), 0.f);
                    prim = fmaf(r, r, prim);
                    gate = fmaf(wv, r, gate);
                }
                nn = fmaf(0.5f * prim, gate, nn);
            }
            v = av + fmaf(lin, tv, nn);
        }
        mn = fminf(mn, v);
    }
    if (mn <= 0.f) {
        const float corr = EPSV - mn;
        for (int i = 0; i < T; ++i) {
            const float tv = t[i];
            float v;
            if (wb_nonneg && tv >= 0.f) {
                v = av + fmaf(lin, tv, fmaf(fmaf(fmaf(c3, tv, c2), tv, c1), tv, c0));
            } else {
                float nn = 0.f;
                for (int k = 0; k < KU; ++k) {
                    float prim = 0.f, gate = 0.f;
                    for (int n = 0; n < NU; ++n) {
                        const float wv = __ldg(&W[k * NU + n]);
                        const float bv = __ldg(&b[k * NU + n]);
                        const float r  = fmaxf(fmaf(wv, tv, bv), 0.f);
                        prim = fmaf(r, r, prim);
                        gate = fmaf(wv, r, gate);
                    }
                    nn = fmaf(0.5f * prim, gate, nn);
                }
                v = av + fmaf(lin, tv, nn);
            }
            out[i] = v + corr;
        }
    }
}

// ---------------------------------------------------------------------------
extern "C" void kernel_launch(void* const* d_in, const int* in_sizes, int n_in,
                              void* d_out, int out_size) {
    const float* t = (const float*)d_in[0];
    const float* W = (const float*)d_in[1];
    const float* b = (const float*)d_in[2];
    const float* V = (const float*)d_in[3];
    const float* a = (const float*)d_in[4];
    float* out = (float*)d_out;

    const int T    = in_sizes[0];
    const int vlen = in_sizes[3];

    const int T4 = T >> 2;
    int nblocks = (T4 + 511) / 512;
    if (nblocks < 1) nblocks = 1;

    fused_mgn_kernel<<<nblocks, 512>>>(t, W, b, V, a, out, T, vlen, nblocks);
}